// round 5
// baseline (speedup 1.0000x reference)
#include <cuda_runtime.h>
#include <math_constants.h>

#define BB 8
#define NN 300
#define RR 36
#define CC 256
#define IOU_THR 0.7f
#define CONF_THR 0.3f
#define GG 14            // OUT * SR sample grid per dim
#define NSAMP 196.0f     // 14*14

// Scratch (no allocations allowed): selected boxes + validity per (b, r)
__device__ float g_sel_boxes[BB * RR * 4];
__device__ int   g_sel_valid[BB * RR];

// ---------------------------------------------------------------------------
// Kernel 1: per-batch stable sort by score (desc) + sequential greedy NMS +
// selection of first R kept boxes.
// ---------------------------------------------------------------------------
__global__ void nms_kernel(const float* __restrict__ boxes,
                           const float* __restrict__ scores) {
    __shared__ float rawsc[NN];
    __shared__ float bx[NN][4];
    __shared__ float area[NN];
    __shared__ int   keep[NN];

    const int b = blockIdx.x;
    const int t = threadIdx.x;
    const int nt = blockDim.x;

    // Load raw scores
    for (int i = t; i < NN; i += nt) rawsc[i] = scores[b * NN + i];
    __syncthreads();

    // Stable descending rank: key = -s (s = score if > CONF_THR else -inf),
    // ties broken by original index ascending (matches jnp.argsort stable).
    for (int i = t; i < NN; i += nt) {
        float si = rawsc[i] > CONF_THR ? rawsc[i] : -CUDART_INF_F;
        int rank = 0;
        for (int j = 0; j < NN; j++) {
            float sj = rawsc[j] > CONF_THR ? rawsc[j] : -CUDART_INF_F;
            if (sj > si || (sj == si && j < i)) rank++;
        }
        // Scatter into sorted position
        const float* bp = boxes + (size_t)(b * NN + i) * 4;
        bx[rank][0] = bp[0];
        bx[rank][1] = bp[1];
        bx[rank][2] = bp[2];
        bx[rank][3] = bp[3];
        keep[rank] = (rawsc[i] > CONF_THR) ? 1 : 0;
    }
    __syncthreads();

    for (int i = t; i < NN; i += nt)
        area[i] = (bx[i][2] - bx[i][0]) * (bx[i][3] - bx[i][1]);
    __syncthreads();

    // Sequential greedy NMS (exact match of the fori_loop semantics)
    for (int i = 0; i < NN; i++) {
        if (keep[i]) {
            const float x1 = bx[i][0], y1 = bx[i][1];
            const float x2 = bx[i][2], y2 = bx[i][3];
            const float ai = area[i];
            for (int j = i + 1 + t; j < NN; j += nt) {
                if (keep[j]) {
                    float lt0 = fmaxf(x1, bx[j][0]);
                    float lt1 = fmaxf(y1, bx[j][1]);
                    float rb0 = fminf(x2, bx[j][2]);
                    float rb1 = fminf(y2, bx[j][3]);
                    float w = fmaxf(rb0 - lt0, 0.0f);
                    float h = fmaxf(rb1 - lt1, 0.0f);
                    float inter = w * h;
                    float iou = inter / (ai + area[j] - inter + 1e-9f);
                    if (iou > IOU_THR) keep[j] = 0;
                }
            }
        }
        __syncthreads();
    }

    // Selection: first R kept boxes in sorted order; rest invalid (-> zeros).
    if (t == 0) {
        int k = 0;
        for (int i = 0; i < NN && k < RR; i++) {
            if (keep[i]) {
                float* dst = g_sel_boxes + (size_t)(b * RR + k) * 4;
                dst[0] = bx[i][0];
                dst[1] = bx[i][1];
                dst[2] = bx[i][2];
                dst[3] = bx[i][3];
                g_sel_valid[b * RR + k] = 1;
                k++;
            }
        }
        for (; k < RR; k++) {
            float* dst = g_sel_boxes + (size_t)(b * RR + k) * 4;
            dst[0] = dst[1] = dst[2] = dst[3] = 0.0f;
            g_sel_valid[b * RR + k] = 0;
        }
    }
}

// ---------------------------------------------------------------------------
// Kernel 2: ROI-align pooling with separable bilinear weights.
// Block = (b, r), thread = channel.
// out[c] = (1/196) * sum_i sum_j Wy[i]*Wx[j]*F[c, Iy[i], Ix[j]]
// (OOB samples contribute weight 0; the OOB mask is an OR of per-axis
//  conditions so the factorization is exact.)
// ---------------------------------------------------------------------------
__global__ void pool_kernel(const float* __restrict__ f0,
                            const float* __restrict__ f1,
                            const float* __restrict__ f2,
                            const float* __restrict__ f3,
                            float* __restrict__ out) {
    const int br = blockIdx.x;          // b*R + r
    const int b  = br / RR;
    const int c  = threadIdx.x;         // channel

    if (!g_sel_valid[br]) {             // uniform across block
        out[(size_t)br * CC + c] = 0.0f;
        return;
    }

    __shared__ float box[4];
    __shared__ float Wy[2 * GG], Wx[2 * GG];
    __shared__ int   Iy[2 * GG], Ix[2 * GG];

    if (c < 4) box[c] = g_sel_boxes[(size_t)br * 4 + c];
    __syncthreads();

    const float x1 = box[0], y1 = box[1], x2 = box[2], y2 = box[3];

    // Level assignment (same math as reference, fp32)
    const float dx = x2 - x1, dy = y2 - y1;
    const float size = sqrtf(fmaxf(dx * dx + dy * dy, 1e-12f));
    const float lvf = floorf(4.0f + log2f(size * (4.0f / 224.0f)));
    const int lv = (int)(fminf(fmaxf(lvf, 2.0f), 5.0f)) - 2;

    const int H = 200 >> lv;            // 200, 100, 50, 25
    const float* F = (lv == 0) ? f0 : (lv == 1) ? f1 : (lv == 2) ? f2 : f3;

    const float rw = fmaxf(x2 - x1, 1.0f);
    const float rh = fmaxf(y2 - y1, 1.0f);
    const float Hf = (float)H;

    // Build separable weight/index tables (threads 0..13: y, 14..27: x)
    if (c < GG) {
        const float Yv = y1 + rh * ((c + 0.5f) / (float)GG);
        const bool oob = (Yv < -1.0f) || (Yv > Hf);
        const float yc = fminf(fmaxf(Yv, 0.0f), Hf - 1.0f);
        const int y0 = (int)floorf(yc);
        const int yi1 = min(y0 + 1, H - 1);
        const float ly = yc - (float)y0;
        Iy[2 * c]     = y0;  Wy[2 * c]     = oob ? 0.0f : (1.0f - ly);
        Iy[2 * c + 1] = yi1; Wy[2 * c + 1] = oob ? 0.0f : ly;
    } else if (c < 2 * GG) {
        const int a = c - GG;
        const float Xv = x1 + rw * ((a + 0.5f) / (float)GG);
        const bool oob = (Xv < -1.0f) || (Xv > Hf);
        const float xc = fminf(fmaxf(Xv, 0.0f), Hf - 1.0f);
        const int x0 = (int)floorf(xc);
        const int xi1 = min(x0 + 1, H - 1);
        const float lx = xc - (float)x0;
        Ix[2 * a]     = x0;  Wx[2 * a]     = oob ? 0.0f : (1.0f - lx);
        Ix[2 * a + 1] = xi1; Wx[2 * a + 1] = oob ? 0.0f : lx;
    }
    __syncthreads();

    const float* Fc = F + ((size_t)(b * CC + c)) * H * H;

    float acc = 0.0f;
    for (int i = 0; i < 2 * GG; i++) {
        const float wy = Wy[i];
        if (wy == 0.0f) continue;       // uniform across block (shared value)
        const float* row = Fc + (size_t)Iy[i] * H;
        float s = 0.0f;
#pragma unroll
        for (int j = 0; j < 2 * GG; j++) {
            s += Wx[j] * __ldg(&row[Ix[j]]);
        }
        acc += wy * s;
    }
    out[(size_t)br * CC + c] = acc * (1.0f / NSAMP);
}

// ---------------------------------------------------------------------------
extern "C" void kernel_launch(void* const* d_in, const int* in_sizes, int n_in,
                              void* d_out, int out_size) {
    const float* boxes  = (const float*)d_in[0];   // (B, N, 4)
    const float* scores = (const float*)d_in[1];   // (B, N)
    const float* feat0  = (const float*)d_in[2];   // (B, C, 200, 200)
    const float* feat1  = (const float*)d_in[3];   // (B, C, 100, 100)
    const float* feat2  = (const float*)d_in[4];   // (B, C, 50, 50)
    const float* feat3  = (const float*)d_in[5];   // (B, C, 25, 25)
    float* out = (float*)d_out;                    // (B, R, C)

    nms_kernel<<<BB, 320>>>(boxes, scores);
    pool_kernel<<<BB * RR, CC>>>(feat0, feat1, feat2, feat3, out);
}

// round 8
// speedup vs baseline: 1.9411x; 1.9411x over previous
#include <cuda_runtime.h>
#include <math_constants.h>

#define BB 8
#define NN 300
#define RR 36
#define CC 256
#define IOU_THR 0.7f
#define CONF_THR 0.3f
#define GG 14            // OUT * SR sample grid per dim
#define NSAMP 196.0f     // 14*14
#define NW 10            // ceil(300/32) bitmask words

// Scratch (no allocations allowed): selected boxes + validity per (b, r)
__device__ float g_sel_boxes[BB * RR * 4];
__device__ int   g_sel_valid[BB * RR];

// ---------------------------------------------------------------------------
// Kernel 1: per-batch stable sort (rank-based) + adjacency-bitmatrix NMS.
// The greedy suppression loop runs on one warp over bitmask words — no
// block-wide barriers inside the sequential phase.
// ---------------------------------------------------------------------------
__global__ void nms_kernel(const float* __restrict__ boxes,
                           const float* __restrict__ scores) {
    __shared__ float sc[NN];
    __shared__ float bx[NN][4];
    __shared__ float area[NN];
    __shared__ unsigned adj[NN][NW];     // adj[i][w]: bits j>i with iou>thr
    __shared__ unsigned keepw[NW];
    __shared__ unsigned char kf[NN];

    const int b = blockIdx.x;
    const int t = threadIdx.x;
    const int nt = blockDim.x;

    for (int i = t; i < NN; i += nt) sc[i] = scores[b * NN + i];
    __syncthreads();

    // Stable descending rank (ties by original index ascending) + scatter.
    for (int i = t; i < NN; i += nt) {
        float si = sc[i] > CONF_THR ? sc[i] : -CUDART_INF_F;
        int rank = 0;
        for (int j = 0; j < NN; j++) {
            float sj = sc[j] > CONF_THR ? sc[j] : -CUDART_INF_F;
            rank += (sj > si) || (sj == si && j < i);
        }
        const float* bp = boxes + (size_t)(b * NN + i) * 4;
        bx[rank][0] = bp[0];
        bx[rank][1] = bp[1];
        bx[rank][2] = bp[2];
        bx[rank][3] = bp[3];
        kf[rank] = (sc[i] > CONF_THR) ? 1 : 0;
    }
    __syncthreads();

    for (int i = t; i < NN; i += nt)
        area[i] = (bx[i][2] - bx[i][0]) * (bx[i][3] - bx[i][1]);
    if (t < NW) {
        unsigned m = 0;
        for (int u = 0; u < 32; u++) {
            int j = t * 32 + u;
            if (j < NN && kf[j]) m |= 1u << u;
        }
        keepw[t] = m;
    }
    __syncthreads();

    // Adjacency bitmatrix: task = (row i, word w). No atomics needed — each
    // word written by exactly one thread.
    for (int task = t; task < NN * NW; task += nt) {
        const int i = task / NW;
        const int w = task - i * NW;
        const float x1 = bx[i][0], y1 = bx[i][1];
        const float x2 = bx[i][2], y2 = bx[i][3];
        const float ai = area[i];
        unsigned m = 0;
        const int j0 = w * 32;
        const int jend = min(j0 + 32, NN);
        for (int j = max(j0, i + 1); j < jend; j++) {
            float lt0 = fmaxf(x1, bx[j][0]);
            float lt1 = fmaxf(y1, bx[j][1]);
            float rb0 = fminf(x2, bx[j][2]);
            float rb1 = fminf(y2, bx[j][3]);
            float wd = fmaxf(rb0 - lt0, 0.0f);
            float ht = fmaxf(rb1 - lt1, 0.0f);
            float inter = wd * ht;
            float iou = inter / (ai + area[j] - inter + 1e-9f);
            if (iou > IOU_THR) m |= 1u << (j - j0);
        }
        adj[i][w] = m;
    }
    __syncthreads();

    // Sequential greedy propagation on warp 0: keep bitmask in registers.
    if (t < 32) {
        unsigned kw = (t < NW) ? keepw[t] : 0u;
        for (int i = 0; i < NN; i++) {
            unsigned ki = __shfl_sync(0xffffffffu, kw, i >> 5);
            if ((ki >> (i & 31)) & 1u) {
                if (t < NW) kw &= ~adj[i][t];   // adj holds only j>i bits
            }
        }
        if (t < NW) keepw[t] = kw;
    }
    __syncthreads();

    // Selection: first R kept boxes in sorted order; rest invalid (-> zeros).
    if (t == 0) {
        int k = 0;
        for (int i = 0; i < NN && k < RR; i++) {
            if ((keepw[i >> 5] >> (i & 31)) & 1u) {
                float* dst = g_sel_boxes + (size_t)(b * RR + k) * 4;
                dst[0] = bx[i][0];
                dst[1] = bx[i][1];
                dst[2] = bx[i][2];
                dst[3] = bx[i][3];
                g_sel_valid[b * RR + k] = 1;
                k++;
            }
        }
        for (; k < RR; k++) {
            float* dst = g_sel_boxes + (size_t)(b * RR + k) * 4;
            dst[0] = dst[1] = dst[2] = dst[3] = 0.0f;
            g_sel_valid[b * RR + k] = 0;
        }
    }
}

// ---------------------------------------------------------------------------
// Kernel 2: ROI-align pooling, lane = x-sample (coalesced row loads),
// private y-accumulation per lane, one warp reduction per channel.
// Grid: (B*R, 2 channel-halves), 512 threads (16 warps x 8 channels).
//   out[c] = (1/196) * Sum_j Wx[j] * ( Sum_i Wy[i] * F[c, Iy[i], Ix[j]] )
// Zero-weight entries (OOB or exact-zero bilinear weight) compacted away.
// ---------------------------------------------------------------------------
__global__ void __launch_bounds__(512)
pool_kernel(const float* __restrict__ f0,
            const float* __restrict__ f1,
            const float* __restrict__ f2,
            const float* __restrict__ f3,
            float* __restrict__ out) {
    const int br   = blockIdx.x;        // b*R + r
    const int half = blockIdx.y;        // channel half (0..1)
    const int b    = br / RR;
    const int tid  = threadIdx.x;
    const int w    = tid >> 5;          // warp 0..15
    const int lane = tid & 31;

    if (!g_sel_valid[br]) {
        if (tid < 128) out[(size_t)br * CC + half * 128 + tid] = 0.0f;
        return;
    }

    __shared__ float tWy[2 * GG], tWx[2 * GG];
    __shared__ int   tIy[2 * GG], tIx[2 * GG];
    __shared__ float cWy[2 * GG], cWx[2 * GG];
    __shared__ int   cIy[2 * GG], cIx[2 * GG];
    __shared__ int   cnt[2];

    // Box + level (uniform; every thread computes — broadcast loads)
    const float x1 = g_sel_boxes[(size_t)br * 4 + 0];
    const float y1 = g_sel_boxes[(size_t)br * 4 + 1];
    const float x2 = g_sel_boxes[(size_t)br * 4 + 2];
    const float y2 = g_sel_boxes[(size_t)br * 4 + 3];

    const float dx = x2 - x1, dy = y2 - y1;
    const float size = sqrtf(fmaxf(dx * dx + dy * dy, 1e-12f));
    const float lvf = floorf(4.0f + log2f(size * (4.0f / 224.0f)));
    const int lv = (int)(fminf(fmaxf(lvf, 2.0f), 5.0f)) - 2;

    const int H = 200 >> lv;            // 200, 100, 50, 25
    const int HH = H * H;
    const float Hf = (float)H;
    const float* F = (lv == 0) ? f0 : (lv == 1) ? f1 : (lv == 2) ? f2 : f3;

    const float rw = fmaxf(dx, 1.0f);
    const float rh = fmaxf(dy, 1.0f);

    // Raw per-axis weight/index tables (threads 0..13: y; 32..45: x)
    if (tid < GG) {
        const float Yv = y1 + rh * ((tid + 0.5f) / (float)GG);
        const bool oob = (Yv < -1.0f) || (Yv > Hf);
        const float yc = fminf(fmaxf(Yv, 0.0f), Hf - 1.0f);
        const int y0 = (int)floorf(yc);
        const int yi1 = min(y0 + 1, H - 1);
        const float ly = yc - (float)y0;
        tIy[2 * tid]     = y0;  tWy[2 * tid]     = oob ? 0.0f : (1.0f - ly);
        tIy[2 * tid + 1] = yi1; tWy[2 * tid + 1] = oob ? 0.0f : ly;
    } else if (tid >= 32 && tid < 32 + GG) {
        const int a = tid - 32;
        const float Xv = x1 + rw * ((a + 0.5f) / (float)GG);
        const bool oob = (Xv < -1.0f) || (Xv > Hf);
        const float xc = fminf(fmaxf(Xv, 0.0f), Hf - 1.0f);
        const int x0 = (int)floorf(xc);
        const int xi1 = min(x0 + 1, H - 1);
        const float lx = xc - (float)x0;
        tIx[2 * a]     = x0;  tWx[2 * a]     = oob ? 0.0f : (1.0f - lx);
        tIx[2 * a + 1] = xi1; tWx[2 * a + 1] = oob ? 0.0f : lx;
    }
    __syncthreads();

    // Compact out zero-weight entries (serial, 28 items each — trivial)
    if (tid == 0) {
        int n = 0;
        for (int i = 0; i < 2 * GG; i++)
            if (tWy[i] != 0.0f) { cWy[n] = tWy[i]; cIy[n] = tIy[i]; n++; }
        cnt[0] = n;
    }
    if (tid == 32) {
        int n = 0;
        for (int i = 0; i < 2 * GG; i++)
            if (tWx[i] != 0.0f) { cWx[n] = tWx[i]; cIx[n] = tIx[i]; n++; }
        cnt[1] = n;
    }
    __syncthreads();

    const int ny = cnt[0], nx = cnt[1];
    const bool act = (lane < nx);
    const float wx = act ? cWx[lane] : 0.0f;
    const int   ix = act ? cIx[lane] : 0;

    for (int k = 0; k < 8; k++) {
        const int c = half * 128 + w + 16 * k;
        float acc = 0.0f;
        if (act) {
            const float* Fcx = F + ((size_t)(b * CC + c)) * HH + ix;
            float a0 = 0.0f, a1 = 0.0f, a2 = 0.0f, a3 = 0.0f;
            int i = 0;
            for (; i + 4 <= ny; i += 4) {
                a0 += cWy[i]     * __ldg(Fcx + cIy[i]     * H);
                a1 += cWy[i + 1] * __ldg(Fcx + cIy[i + 1] * H);
                a2 += cWy[i + 2] * __ldg(Fcx + cIy[i + 2] * H);
                a3 += cWy[i + 3] * __ldg(Fcx + cIy[i + 3] * H);
            }
            for (; i < ny; i++)
                a0 += cWy[i] * __ldg(Fcx + cIy[i] * H);
            acc = ((a0 + a1) + (a2 + a3)) * wx;
        }
#pragma unroll
        for (int o = 16; o; o >>= 1)
            acc += __shfl_xor_sync(0xffffffffu, acc, o);
        if (lane == 0)
            out[(size_t)br * CC + c] = acc * (1.0f / NSAMP);
    }
}

// ---------------------------------------------------------------------------
extern "C" void kernel_launch(void* const* d_in, const int* in_sizes, int n_in,
                              void* d_out, int out_size) {
    const float* boxes  = (const float*)d_in[0];   // (B, N, 4)
    const float* scores = (const float*)d_in[1];   // (B, N)
    const float* feat0  = (const float*)d_in[2];   // (B, C, 200, 200)
    const float* feat1  = (const float*)d_in[3];   // (B, C, 100, 100)
    const float* feat2  = (const float*)d_in[4];   // (B, C, 50, 50)
    const float* feat3  = (const float*)d_in[5];   // (B, C, 25, 25)
    float* out = (float*)d_out;                    // (B, R, C)

    nms_kernel<<<BB, 320>>>(boxes, scores);
    pool_kernel<<<dim3(BB * RR, 2), 512>>>(feat0, feat1, feat2, feat3, out);
}

// round 10
// speedup vs baseline: 2.7967x; 1.4408x over previous
#include <cuda_runtime.h>
#include <math_constants.h>

#define BB 8
#define NN 300
#define RR 36
#define CC 256
#define IOU_THR 0.7f
#define CONF_THR 0.3f
#define GG 14            // OUT * SR sample grid per dim
#define NSAMP 196.0f     // 14*14
#define NW 10            // ceil(300/32) live bitmask words
#define NWP 12           // padded to 3 x uint4 per row

// Scratch (no allocations allowed): selected boxes + validity per (b, r)
__device__ float g_sel_boxes[BB * RR * 4];
__device__ int   g_sel_valid[BB * RR];

// ---------------------------------------------------------------------------
// Kernel 1: per-batch stable sort (rank-based) + adjacency-bitmatrix NMS.
// Greedy propagation: ONE thread, keep mask in registers (12 words, fully
// unrolled), adjacency rows read as 3x uint4 from padded shared rows.
// Selection: parallel popcount-prefix over the final mask.
// ---------------------------------------------------------------------------
__global__ void __launch_bounds__(320)
nms_kernel(const float* __restrict__ boxes,
           const float* __restrict__ scores) {
    __shared__ float sc[NN];
    __shared__ float bx[NN][4];
    __shared__ float area[NN];
    __shared__ __align__(16) unsigned adj[NN][NWP];  // bits j>i with iou>thr
    __shared__ unsigned fin[NW];

    const int b = blockIdx.x;
    const int t = threadIdx.x;

    if (t < NN) sc[t] = scores[b * NN + t];
    __syncthreads();

    // Stable descending rank (ties by original index ascending) + scatter.
    if (t < NN) {
        const float st_ = sc[t];
        float si = st_ > CONF_THR ? st_ : -CUDART_INF_F;
        int rank = 0;
        for (int j = 0; j < NN; j++) {
            float sj = sc[j] > CONF_THR ? sc[j] : -CUDART_INF_F;
            rank += (sj > si) || (sj == si && j < t);
        }
        const float* bp = boxes + (size_t)(b * NN + t) * 4;
        bx[rank][0] = bp[0];
        bx[rank][1] = bp[1];
        bx[rank][2] = bp[2];
        bx[rank][3] = bp[3];
    }
    __syncthreads();

    if (t < NN)
        area[t] = (bx[t][2] - bx[t][0]) * (bx[t][3] - bx[t][1]);
    // Initial keep mask from conf threshold: after the stable sort, the first
    // K_conf slots hold scores > CONF_THR. Compute count in parallel.
    __shared__ int nconf_sh;
    if (t == 0) nconf_sh = 0;
    __syncthreads();
    if (t < NN && sc[t] > CONF_THR) atomicAdd(&nconf_sh, 1);
    __syncthreads();
    const int nconf = nconf_sh;      // slots [0, nconf) are valid candidates

    // Adjacency bitmatrix rows (padded). task = (row i, word w).
    for (int task = t; task < NN * NWP; task += 320) {
        const int i = task / NWP;
        const int w = task - i * NWP;
        unsigned m = 0;
        if (w < NW) {
            const float x1 = bx[i][0], y1 = bx[i][1];
            const float x2 = bx[i][2], y2 = bx[i][3];
            const float ai = area[i];
            const int j0 = w * 32;
            const int jend = min(j0 + 32, min(NN, nconf));
            for (int j = max(j0, i + 1); j < jend; j++) {
                float lt0 = fmaxf(x1, bx[j][0]);
                float lt1 = fmaxf(y1, bx[j][1]);
                float rb0 = fminf(x2, bx[j][2]);
                float rb1 = fminf(y2, bx[j][3]);
                float wd = fmaxf(rb0 - lt0, 0.0f);
                float ht = fmaxf(rb1 - lt1, 0.0f);
                float inter = wd * ht;
                float iou = inter / (ai + area[j] - inter + 1e-9f);
                if (iou > IOU_THR) m |= 1u << (j - j0);
            }
        }
        adj[i][w] = m;
    }
    __syncthreads();

    // Sequential greedy on one thread, registers only.
    if (t == 0) {
        unsigned kw[NWP];
#pragma unroll
        for (int w = 0; w < NWP; w++) {
            int lo = w * 32;
            if (lo >= nconf) kw[w] = 0u;
            else if (lo + 32 <= nconf) kw[w] = 0xffffffffu;
            else kw[w] = (1u << (nconf - lo)) - 1u;
        }
#pragma unroll
        for (int wo = 0; wo < NW; wo++) {
            unsigned rem = kw[wo];
            while (rem) {
                const int bit = __ffs(rem) - 1;
                const int i = wo * 32 + bit;
                const uint4* row = (const uint4*)&adj[i][0];
                uint4 r0 = row[0], r1 = row[1], r2 = row[2];
                kw[0] &= ~r0.x;  kw[1] &= ~r0.y;  kw[2]  &= ~r0.z;  kw[3]  &= ~r0.w;
                kw[4] &= ~r1.x;  kw[5] &= ~r1.y;  kw[6]  &= ~r1.z;  kw[7]  &= ~r1.w;
                kw[8] &= ~r2.x;  kw[9] &= ~r2.y;  kw[10] &= ~r2.z;  kw[11] &= ~r2.w;
                rem &= ~(1u << bit);
                rem &= kw[wo];           // adj holds only j>i bits — safe
            }
        }
#pragma unroll
        for (int w = 0; w < NW; w++) fin[w] = kw[w];
    }
    __syncthreads();

    // Parallel selection: kept boxes in sorted order -> slots [0, K).
    if (t < NN) {
        const int wo = t >> 5, bit = t & 31;
        if ((fin[wo] >> bit) & 1u) {
            int pre = __popc(fin[wo] & ((bit ? ((1u << bit) - 1u) : 0u)));
            for (int w = 0; w < wo; w++) pre += __popc(fin[w]);
            if (pre < RR) {
                float* dst = g_sel_boxes + (size_t)(b * RR + pre) * 4;
                dst[0] = bx[t][0];
                dst[1] = bx[t][1];
                dst[2] = bx[t][2];
                dst[3] = bx[t][3];
                g_sel_valid[b * RR + pre] = 1;
            }
        }
    }
    if (t < RR) {
        int K = 0;
        for (int w = 0; w < NW; w++) K += __popc(fin[w]);
        if (t >= K) {
            float* dst = g_sel_boxes + (size_t)(b * RR + t) * 4;
            dst[0] = dst[1] = dst[2] = dst[3] = 0.0f;
            g_sel_valid[b * RR + t] = 0;
        }
    }
}

// ---------------------------------------------------------------------------
// Kernel 2: ROI-align pooling, lane = x-sample, 2 channels in flight per
// iteration (MLP 8), precomputed row byte-offsets, 4-way channel split.
// Grid: (B*R, 4 quarters), 256 threads (8 warps x 8 channel-slots).
// ---------------------------------------------------------------------------
__global__ void __launch_bounds__(256)
pool_kernel(const float* __restrict__ f0,
            const float* __restrict__ f1,
            const float* __restrict__ f2,
            const float* __restrict__ f3,
            float* __restrict__ out) {
    const int br   = blockIdx.x;        // b*R + r
    const int q    = blockIdx.y;        // channel quarter (0..3)
    const int b    = br / RR;
    const int tid  = threadIdx.x;
    const int w    = tid >> 5;          // warp 0..7
    const int lane = tid & 31;

    if (!g_sel_valid[br]) {
        if (tid < 64) out[(size_t)br * CC + q * 64 + tid] = 0.0f;
        return;
    }

    __shared__ float tWy[2 * GG], tWx[2 * GG];
    __shared__ int   tIy[2 * GG], tIx[2 * GG];
    __shared__ float cWy[2 * GG], cWx[2 * GG];
    __shared__ int   cOy[2 * GG], cIx[2 * GG];   // cOy = Iy * H (elements)
    __shared__ int   cnt[2];

    const float x1 = g_sel_boxes[(size_t)br * 4 + 0];
    const float y1 = g_sel_boxes[(size_t)br * 4 + 1];
    const float x2 = g_sel_boxes[(size_t)br * 4 + 2];
    const float y2 = g_sel_boxes[(size_t)br * 4 + 3];

    const float dx = x2 - x1, dy = y2 - y1;
    const float size = sqrtf(fmaxf(dx * dx + dy * dy, 1e-12f));
    const float lvf = floorf(4.0f + log2f(size * (4.0f / 224.0f)));
    const int lv = (int)(fminf(fmaxf(lvf, 2.0f), 5.0f)) - 2;

    const int H = 200 >> lv;            // 200, 100, 50, 25
    const int HH = H * H;
    const float Hf = (float)H;
    const float* F = (lv == 0) ? f0 : (lv == 1) ? f1 : (lv == 2) ? f2 : f3;

    const float rw = fmaxf(dx, 1.0f);
    const float rh = fmaxf(dy, 1.0f);

    if (tid < GG) {
        const float Yv = y1 + rh * ((tid + 0.5f) / (float)GG);
        const bool oob = (Yv < -1.0f) || (Yv > Hf);
        const float yc = fminf(fmaxf(Yv, 0.0f), Hf - 1.0f);
        const int y0 = (int)floorf(yc);
        const int yi1 = min(y0 + 1, H - 1);
        const float ly = yc - (float)y0;
        tIy[2 * tid]     = y0;  tWy[2 * tid]     = oob ? 0.0f : (1.0f - ly);
        tIy[2 * tid + 1] = yi1; tWy[2 * tid + 1] = oob ? 0.0f : ly;
    } else if (tid >= 32 && tid < 32 + GG) {
        const int a = tid - 32;
        const float Xv = x1 + rw * ((a + 0.5f) / (float)GG);
        const bool oob = (Xv < -1.0f) || (Xv > Hf);
        const float xc = fminf(fmaxf(Xv, 0.0f), Hf - 1.0f);
        const int x0 = (int)floorf(xc);
        const int xi1 = min(x0 + 1, H - 1);
        const float lx = xc - (float)x0;
        tIx[2 * a]     = x0;  tWx[2 * a]     = oob ? 0.0f : (1.0f - lx);
        tIx[2 * a + 1] = xi1; tWx[2 * a + 1] = oob ? 0.0f : lx;
    }
    __syncthreads();

    if (tid == 0) {
        int n = 0;
        for (int i = 0; i < 2 * GG; i++)
            if (tWy[i] != 0.0f) { cWy[n] = tWy[i]; cOy[n] = tIy[i] * H; n++; }
        cnt[0] = n;
    }
    if (tid == 32) {
        int n = 0;
        for (int i = 0; i < 2 * GG; i++)
            if (tWx[i] != 0.0f) { cWx[n] = tWx[i]; cIx[n] = tIx[i]; n++; }
        cnt[1] = n;
    }
    __syncthreads();

    const int ny = cnt[0], nx = cnt[1];
    const bool act = (lane < nx);
    const float wx = act ? cWx[lane] : 0.0f;
    const int   ix = act ? cIx[lane] : 0;

    const float* Fbase = F + (size_t)(b * CC + q * 64) * HH + ix;

#pragma unroll
    for (int k = 0; k < 4; k++) {
        const int c0 = w + 8 * k;          // channel-slot within quarter
        const int c1 = c0 + 32;
        float s0 = 0.0f, s1 = 0.0f;
        if (act) {
            const float* F0 = Fbase + (size_t)c0 * HH;
            const float* F1 = Fbase + (size_t)c1 * HH;
            float a00 = 0.0f, a01 = 0.0f, a10 = 0.0f, a11 = 0.0f;
            int i = 0;
            for (; i + 2 <= ny; i += 2) {
                const int o0 = cOy[i], o1 = cOy[i + 1];
                const float w0 = cWy[i], w1 = cWy[i + 1];
                a00 += w0 * __ldg(F0 + o0);
                a10 += w0 * __ldg(F1 + o0);
                a01 += w1 * __ldg(F0 + o1);
                a11 += w1 * __ldg(F1 + o1);
            }
            if (i < ny) {
                const int o0 = cOy[i];
                const float w0 = cWy[i];
                a00 += w0 * __ldg(F0 + o0);
                a10 += w0 * __ldg(F1 + o0);
            }
            s0 = (a00 + a01) * wx;
            s1 = (a10 + a11) * wx;
        }
#pragma unroll
        for (int o = 16; o; o >>= 1) {
            s0 += __shfl_xor_sync(0xffffffffu, s0, o);
            s1 += __shfl_xor_sync(0xffffffffu, s1, o);
        }
        if (lane == 0) {
            out[(size_t)br * CC + q * 64 + c0] = s0 * (1.0f / NSAMP);
            out[(size_t)br * CC + q * 64 + c1] = s1 * (1.0f / NSAMP);
        }
    }
}

// ---------------------------------------------------------------------------
extern "C" void kernel_launch(void* const* d_in, const int* in_sizes, int n_in,
                              void* d_out, int out_size) {
    const float* boxes  = (const float*)d_in[0];   // (B, N, 4)
    const float* scores = (const float*)d_in[1];   // (B, N)
    const float* feat0  = (const float*)d_in[2];   // (B, C, 200, 200)
    const float* feat1  = (const float*)d_in[3];   // (B, C, 100, 100)
    const float* feat2  = (const float*)d_in[4];   // (B, C, 50, 50)
    const float* feat3  = (const float*)d_in[5];   // (B, C, 25, 25)
    float* out = (float*)d_out;                    // (B, R, C)

    nms_kernel<<<BB, 320>>>(boxes, scores);
    pool_kernel<<<dim3(BB * RR, 4), 256>>>(feat0, feat1, feat2, feat3, out);
}

// round 11
// speedup vs baseline: 3.7158x; 1.3287x over previous
#include <cuda_runtime.h>
#include <math_constants.h>

#define BB 8
#define NN 300
#define RR 36
#define CC 256
#define IOU_THR 0.7f
#define CONF_THR 0.3f
#define GG 14            // OUT * SR sample grid per dim
#define NSAMP 196.0f     // 14*14
#define NW 10            // ceil(300/32) live bitmask words
#define NWP 12           // padded to 3 x uint4 per row

// Scratch (no allocations allowed): selected boxes + validity per (b, r)
__device__ float g_sel_boxes[BB * RR * 4];
__device__ int   g_sel_valid[BB * RR];

// ---------------------------------------------------------------------------
// Kernel 1: per-batch stable sort (rank-based) + adjacency-bitmatrix NMS.
// 1024 threads: adjacency build 3.2x wider than R10. Rows i >= nconf skipped
// entirely (greedy never reads them). Boxes held as float4 (LDS.128).
// Greedy propagation: ONE thread, keep mask in registers.
// Selection: parallel popcount-prefix over the final mask.
// ---------------------------------------------------------------------------
__global__ void __launch_bounds__(1024)
nms_kernel(const float* __restrict__ boxes,
           const float* __restrict__ scores) {
    __shared__ float sc[NN];
    __shared__ __align__(16) float4 bx4[NN];
    __shared__ float area[NN];
    __shared__ __align__(16) unsigned adj[NN][NWP];  // bits j>i with iou>thr
    __shared__ unsigned fin[NW];
    __shared__ int nconf_sh;

    const int b = blockIdx.x;
    const int t = threadIdx.x;

    if (t == 0) nconf_sh = 0;
    if (t < NN) sc[t] = scores[b * NN + t];
    __syncthreads();

    // Stable descending rank (ties by original index ascending) + scatter.
    if (t < NN) {
        const float st_ = sc[t];
        float si = st_ > CONF_THR ? st_ : -CUDART_INF_F;
        int rank = 0;
#pragma unroll 4
        for (int j = 0; j < NN; j++) {
            float sj = sc[j] > CONF_THR ? sc[j] : -CUDART_INF_F;
            rank += (sj > si) || (sj == si && j < t);
        }
        bx4[rank] = ((const float4*)boxes)[b * NN + t];
        if (st_ > CONF_THR) atomicAdd(&nconf_sh, 1);
    }
    __syncthreads();

    if (t < NN) {
        float4 v = bx4[t];
        area[t] = (v.z - v.x) * (v.w - v.y);
    }
    __syncthreads();
    const int nconf = nconf_sh;      // slots [0, nconf) are valid candidates

    // Adjacency bitmatrix rows (padded). task = (row i, word w).
    // Only rows i < nconf matter; others zero-filled (padding words too).
    for (int task = t; task < NN * NWP; task += 1024) {
        const int i = task / NWP;
        const int w = task - i * NWP;
        unsigned m = 0;
        if (w < NW && i < nconf) {
            const float4 bi = bx4[i];
            const float ai = area[i];
            const int j0 = w * 32;
            const int jend = min(j0 + 32, nconf);
            for (int j = max(j0, i + 1); j < jend; j++) {
                const float4 bj = bx4[j];
                float lt0 = fmaxf(bi.x, bj.x);
                float lt1 = fmaxf(bi.y, bj.y);
                float rb0 = fminf(bi.z, bj.z);
                float rb1 = fminf(bi.w, bj.w);
                float wd = fmaxf(rb0 - lt0, 0.0f);
                float ht = fmaxf(rb1 - lt1, 0.0f);
                float inter = wd * ht;
                float iou = inter / (ai + area[j] - inter + 1e-9f);
                if (iou > IOU_THR) m |= 1u << (j - j0);
            }
        }
        adj[i][w] = m;
    }
    __syncthreads();

    // Sequential greedy on one thread, registers only.
    if (t == 0) {
        const int nwc = (nconf + 31) >> 5;   // live words
        unsigned kw[NWP];
#pragma unroll
        for (int w = 0; w < NWP; w++) {
            int lo = w * 32;
            if (lo >= nconf) kw[w] = 0u;
            else if (lo + 32 <= nconf) kw[w] = 0xffffffffu;
            else kw[w] = (1u << (nconf - lo)) - 1u;
        }
        for (int wo = 0; wo < nwc; wo++) {
            unsigned rem = kw[wo];
            while (rem) {
                const int bit = __ffs(rem) - 1;
                const int i = wo * 32 + bit;
                const uint4* row = (const uint4*)&adj[i][0];
                uint4 r0 = row[0], r1 = row[1], r2 = row[2];
                kw[0] &= ~r0.x;  kw[1] &= ~r0.y;  kw[2]  &= ~r0.z;  kw[3]  &= ~r0.w;
                kw[4] &= ~r1.x;  kw[5] &= ~r1.y;  kw[6]  &= ~r1.z;  kw[7]  &= ~r1.w;
                kw[8] &= ~r2.x;  kw[9] &= ~r2.y;  kw[10] &= ~r2.z;  kw[11] &= ~r2.w;
                rem &= ~(1u << bit);
                rem &= kw[wo];           // adj holds only j>i bits — safe
            }
        }
#pragma unroll
        for (int w = 0; w < NW; w++) fin[w] = kw[w];
    }
    __syncthreads();

    // Parallel selection: kept boxes in sorted order -> slots [0, K).
    if (t < NN) {
        const int wo = t >> 5, bit = t & 31;
        if ((fin[wo] >> bit) & 1u) {
            int pre = __popc(fin[wo] & (bit ? ((1u << bit) - 1u) : 0u));
            for (int w = 0; w < wo; w++) pre += __popc(fin[w]);
            if (pre < RR) {
                const float4 v = bx4[t];
                float* dst = g_sel_boxes + (size_t)(b * RR + pre) * 4;
                dst[0] = v.x; dst[1] = v.y; dst[2] = v.z; dst[3] = v.w;
                g_sel_valid[b * RR + pre] = 1;
            }
        }
    }
    if (t < RR) {
        int K = 0;
        for (int w = 0; w < NW; w++) K += __popc(fin[w]);
        if (t >= K) {
            float* dst = g_sel_boxes + (size_t)(b * RR + t) * 4;
            dst[0] = dst[1] = dst[2] = dst[3] = 0.0f;
            g_sel_valid[b * RR + t] = 0;
        }
    }
}

// ---------------------------------------------------------------------------
// Kernel 2: ROI-align pooling, lane = x-sample, 4 channels in flight per
// warp (8 independent LDGs per y-pair iteration), 8-way channel split.
// Grid: (B*R, 8 eighths), 256 threads (8 warps; warp w covers channels
// e*32 + {w, w+8, w+16, w+24}).
// ---------------------------------------------------------------------------
__global__ void __launch_bounds__(256)
pool_kernel(const float* __restrict__ f0,
            const float* __restrict__ f1,
            const float* __restrict__ f2,
            const float* __restrict__ f3,
            float* __restrict__ out) {
    const int br   = blockIdx.x;        // b*R + r
    const int e    = blockIdx.y;        // channel eighth (0..7)
    const int b    = br / RR;
    const int tid  = threadIdx.x;
    const int w    = tid >> 5;          // warp 0..7
    const int lane = tid & 31;

    if (!g_sel_valid[br]) {
        if (tid < 32) out[(size_t)br * CC + e * 32 + tid] = 0.0f;
        return;
    }

    __shared__ float tWy[2 * GG], tWx[2 * GG];
    __shared__ int   tIy[2 * GG], tIx[2 * GG];
    __shared__ float cWy[2 * GG], cWx[2 * GG];
    __shared__ int   cOy[2 * GG], cIx[2 * GG];   // cOy = Iy * H (elements)
    __shared__ int   cnt[2];

    const float x1 = g_sel_boxes[(size_t)br * 4 + 0];
    const float y1 = g_sel_boxes[(size_t)br * 4 + 1];
    const float x2 = g_sel_boxes[(size_t)br * 4 + 2];
    const float y2 = g_sel_boxes[(size_t)br * 4 + 3];

    const float dx = x2 - x1, dy = y2 - y1;
    const float size = sqrtf(fmaxf(dx * dx + dy * dy, 1e-12f));
    const float lvf = floorf(4.0f + log2f(size * (4.0f / 224.0f)));
    const int lv = (int)(fminf(fmaxf(lvf, 2.0f), 5.0f)) - 2;

    const int H = 200 >> lv;            // 200, 100, 50, 25
    const int HH = H * H;
    const float Hf = (float)H;
    const float* F = (lv == 0) ? f0 : (lv == 1) ? f1 : (lv == 2) ? f2 : f3;

    const float rw = fmaxf(dx, 1.0f);
    const float rh = fmaxf(dy, 1.0f);

    if (tid < GG) {
        const float Yv = y1 + rh * ((tid + 0.5f) / (float)GG);
        const bool oob = (Yv < -1.0f) || (Yv > Hf);
        const float yc = fminf(fmaxf(Yv, 0.0f), Hf - 1.0f);
        const int y0 = (int)floorf(yc);
        const int yi1 = min(y0 + 1, H - 1);
        const float ly = yc - (float)y0;
        tIy[2 * tid]     = y0;  tWy[2 * tid]     = oob ? 0.0f : (1.0f - ly);
        tIy[2 * tid + 1] = yi1; tWy[2 * tid + 1] = oob ? 0.0f : ly;
    } else if (tid >= 32 && tid < 32 + GG) {
        const int a = tid - 32;
        const float Xv = x1 + rw * ((a + 0.5f) / (float)GG);
        const bool oob = (Xv < -1.0f) || (Xv > Hf);
        const float xc = fminf(fmaxf(Xv, 0.0f), Hf - 1.0f);
        const int x0 = (int)floorf(xc);
        const int xi1 = min(x0 + 1, H - 1);
        const float lx = xc - (float)x0;
        tIx[2 * a]     = x0;  tWx[2 * a]     = oob ? 0.0f : (1.0f - lx);
        tIx[2 * a + 1] = xi1; tWx[2 * a + 1] = oob ? 0.0f : lx;
    }
    __syncthreads();

    if (tid == 0) {
        int n = 0;
        for (int i = 0; i < 2 * GG; i++)
            if (tWy[i] != 0.0f) { cWy[n] = tWy[i]; cOy[n] = tIy[i] * H; n++; }
        cnt[0] = n;
    }
    if (tid == 32) {
        int n = 0;
        for (int i = 0; i < 2 * GG; i++)
            if (tWx[i] != 0.0f) { cWx[n] = tWx[i]; cIx[n] = tIx[i]; n++; }
        cnt[1] = n;
    }
    __syncthreads();

    const int ny = cnt[0], nx = cnt[1];
    const bool act = (lane < nx);
    const float wx = act ? cWx[lane] : 0.0f;
    const int   ix = act ? cIx[lane] : 0;

    float a0 = 0.0f, a1 = 0.0f, a2 = 0.0f, a3 = 0.0f;
    if (act) {
        const float* F0 = F + (size_t)(b * CC + e * 32 + w) * HH + ix;
        const float* F1 = F0 + (size_t)8  * HH;
        const float* F2 = F0 + (size_t)16 * HH;
        const float* F3 = F0 + (size_t)24 * HH;
        int i = 0;
        for (; i + 2 <= ny; i += 2) {
            const int o0 = cOy[i], o1 = cOy[i + 1];
            const float w0 = cWy[i], w1 = cWy[i + 1];
            a0 += w0 * __ldg(F0 + o0) + w1 * __ldg(F0 + o1);
            a1 += w0 * __ldg(F1 + o0) + w1 * __ldg(F1 + o1);
            a2 += w0 * __ldg(F2 + o0) + w1 * __ldg(F2 + o1);
            a3 += w0 * __ldg(F3 + o0) + w1 * __ldg(F3 + o1);
        }
        if (i < ny) {
            const int o0 = cOy[i];
            const float w0 = cWy[i];
            a0 += w0 * __ldg(F0 + o0);
            a1 += w0 * __ldg(F1 + o0);
            a2 += w0 * __ldg(F2 + o0);
            a3 += w0 * __ldg(F3 + o0);
        }
        a0 *= wx; a1 *= wx; a2 *= wx; a3 *= wx;
    }
#pragma unroll
    for (int o = 16; o; o >>= 1) {
        a0 += __shfl_xor_sync(0xffffffffu, a0, o);
        a1 += __shfl_xor_sync(0xffffffffu, a1, o);
        a2 += __shfl_xor_sync(0xffffffffu, a2, o);
        a3 += __shfl_xor_sync(0xffffffffu, a3, o);
    }
    if (lane == 0) {
        float* ob = out + (size_t)br * CC + e * 32 + w;
        ob[0]  = a0 * (1.0f / NSAMP);
        ob[8]  = a1 * (1.0f / NSAMP);
        ob[16] = a2 * (1.0f / NSAMP);
        ob[24] = a3 * (1.0f / NSAMP);
    }
}

// ---------------------------------------------------------------------------
extern "C" void kernel_launch(void* const* d_in, const int* in_sizes, int n_in,
                              void* d_out, int out_size) {
    const float* boxes  = (const float*)d_in[0];   // (B, N, 4)
    const float* scores = (const float*)d_in[1];   // (B, N)
    const float* feat0  = (const float*)d_in[2];   // (B, C, 200, 200)
    const float* feat1  = (const float*)d_in[3];   // (B, C, 100, 100)
    const float* feat2  = (const float*)d_in[4];   // (B, C, 50, 50)
    const float* feat3  = (const float*)d_in[5];   // (B, C, 25, 25)
    float* out = (float*)d_out;                    // (B, R, C)

    nms_kernel<<<BB, 1024>>>(boxes, scores);
    pool_kernel<<<dim3(BB * RR, 8), 256>>>(feat0, feat1, feat2, feat3, out);
}

// round 13
// speedup vs baseline: 5.1339x; 1.3816x over previous
#include <cuda_runtime.h>
#include <math_constants.h>

#define BB 8
#define NN 300
#define RR 36
#define CC 256
#define IOU_THR 0.7f
#define CONF_THR 0.3f
#define GG 14            // OUT * SR sample grid per dim
#define NSAMP 196.0f     // 14*14
#define NW 10            // ceil(300/32) live bitmask words
#define NWP 12           // padded to 3 x uint4 per row

// Scratch (no allocations allowed)
__device__ __align__(16) float4   g_sorted[BB][NN];
__device__ float                  g_area[BB][NN];
__device__ int                    g_nconf[BB];
__device__ __align__(16) unsigned g_adj[BB][NN][NWP];
__device__ float g_sel_boxes[BB * RR * 4];
__device__ int   g_sel_valid[BB * RR];

// ---------------------------------------------------------------------------
// N1: stable descending rank (3-way chunked partial ranks + shared atomics),
// scatter sorted boxes + areas + nconf to global scratch. 8 blocks.
// ---------------------------------------------------------------------------
__global__ void __launch_bounds__(1024)
nms_rank_kernel(const float* __restrict__ boxes,
                const float* __restrict__ scores) {
    __shared__ float sc[NN];
    __shared__ int rankq[NN];
    __shared__ int nconf_sh;

    const int b = blockIdx.x;
    const int t = threadIdx.x;

    if (t == 0) nconf_sh = 0;
    if (t < NN) { sc[t] = scores[b * NN + t]; rankq[t] = 0; }
    __syncthreads();

    // Partial ranks: task = (i, chunk k of 100 j's). 900 tasks.
    if (t < 3 * NN) {
        const int i = t % NN;
        const int k = t / NN;            // 0..2
        const float si0 = sc[i];
        const float si = si0 > CONF_THR ? si0 : -CUDART_INF_F;
        const int j0 = k * 100, j1 = j0 + 100;
        int r = 0;
#pragma unroll 4
        for (int j = j0; j < j1; j++) {
            float sj = sc[j] > CONF_THR ? sc[j] : -CUDART_INF_F;
            r += (sj > si) || (sj == si && j < i);
        }
        if (r) atomicAdd(&rankq[i], r);
    }
    if (t < NN && sc[t] > CONF_THR) atomicAdd(&nconf_sh, 1);
    __syncthreads();

    if (t < NN) {
        const float4 v = ((const float4*)boxes)[b * NN + t];
        const int r = rankq[t];
        g_sorted[b][r] = v;
        g_area[b][r] = (v.z - v.x) * (v.w - v.y);
    }
    if (t == 0) g_nconf[b] = nconf_sh;
}

// ---------------------------------------------------------------------------
// N2: adjacency word w (32 j's) for all rows i. Grid (8, 12) — 96 blocks in
// parallel across SMs. j-boxes cached in smem (broadcast LDS inner loop).
// ---------------------------------------------------------------------------
__global__ void __launch_bounds__(320)
nms_adj_kernel() {
    const int b = blockIdx.x;
    const int w = blockIdx.y;            // 0..NWP-1
    const int t = threadIdx.x;

    __shared__ float4 bj[32];
    __shared__ float  aj[32];

    const int nconf = g_nconf[b];
    const int j0 = w * 32;
    const int jend = min(j0 + 32, nconf);

    if (t < 32) {
        const int j = j0 + t;
        if (j < jend) { bj[t] = g_sorted[b][j]; aj[t] = g_area[b][j]; }
    }
    __syncthreads();

    if (t < NN) {
        unsigned m = 0;
        if (w < NW && t < nconf) {
            const float4 bi = g_sorted[b][t];
            const float ai = g_area[b][t];
            for (int j = max(j0, t + 1); j < jend; j++) {
                const float4 bv = bj[j - j0];
                float lt0 = fmaxf(bi.x, bv.x);
                float lt1 = fmaxf(bi.y, bv.y);
                float rb0 = fminf(bi.z, bv.z);
                float rb1 = fminf(bi.w, bv.w);
                float wd = fmaxf(rb0 - lt0, 0.0f);
                float ht = fmaxf(rb1 - lt1, 0.0f);
                float inter = wd * ht;
                float iou = inter / (ai + aj[j - j0] - inter + 1e-9f);
                if (iou > IOU_THR) m |= 1u << (j - j0);
            }
        }
        g_adj[b][t][w] = m;
    }
}

// ---------------------------------------------------------------------------
// N3: bulk-load adjacency into smem (coalesced uint4), register-resident
// single-thread greedy, parallel popcount-prefix selection. 8 blocks.
// ---------------------------------------------------------------------------
__global__ void __launch_bounds__(512)
nms_greedy_kernel() {
    __shared__ __align__(16) unsigned adj[NN][NWP];
    __shared__ __align__(16) float4 bx4[NN];
    __shared__ unsigned fin[NW];

    const int b = blockIdx.x;
    const int t = threadIdx.x;
    const int nconf = g_nconf[b];

    for (int idx = t; idx < NN * NWP / 4; idx += 512)
        ((uint4*)adj)[idx] = ((const uint4*)g_adj[b])[idx];
    for (int idx = t; idx < NN; idx += 512)
        bx4[idx] = g_sorted[b][idx];
    __syncthreads();

    if (t == 0) {
        const int nwc = (nconf + 31) >> 5;
        unsigned kw[NWP];
#pragma unroll
        for (int w = 0; w < NWP; w++) {
            int lo = w * 32;
            if (lo >= nconf) kw[w] = 0u;
            else if (lo + 32 <= nconf) kw[w] = 0xffffffffu;
            else kw[w] = (1u << (nconf - lo)) - 1u;
        }
        for (int wo = 0; wo < nwc; wo++) {
            unsigned rem = kw[wo];
            while (rem) {
                const int bit = __ffs(rem) - 1;
                const int i = wo * 32 + bit;
                const uint4* row = (const uint4*)&adj[i][0];
                uint4 r0 = row[0], r1 = row[1], r2 = row[2];
                kw[0] &= ~r0.x;  kw[1] &= ~r0.y;  kw[2]  &= ~r0.z;  kw[3]  &= ~r0.w;
                kw[4] &= ~r1.x;  kw[5] &= ~r1.y;  kw[6]  &= ~r1.z;  kw[7]  &= ~r1.w;
                kw[8] &= ~r2.x;  kw[9] &= ~r2.y;  kw[10] &= ~r2.z;  kw[11] &= ~r2.w;
                rem &= ~(1u << bit);
                rem &= kw[wo];           // adj holds only j>i bits — safe
            }
        }
#pragma unroll
        for (int w = 0; w < NW; w++) fin[w] = kw[w];
    }
    __syncthreads();

    if (t < NN) {
        const int wo = t >> 5, bit = t & 31;
        if ((fin[wo] >> bit) & 1u) {
            int pre = __popc(fin[wo] & (bit ? ((1u << bit) - 1u) : 0u));
            for (int w = 0; w < wo; w++) pre += __popc(fin[w]);
            if (pre < RR) {
                const float4 v = bx4[t];
                float* dst = g_sel_boxes + (size_t)(b * RR + pre) * 4;
                dst[0] = v.x; dst[1] = v.y; dst[2] = v.z; dst[3] = v.w;
                g_sel_valid[b * RR + pre] = 1;
            }
        }
    }
    if (t < RR) {
        int K = 0;
        for (int w = 0; w < NW; w++) K += __popc(fin[w]);
        if (t >= K) {
            float* dst = g_sel_boxes + (size_t)(b * RR + t) * 4;
            dst[0] = dst[1] = dst[2] = dst[3] = 0.0f;
            g_sel_valid[b * RR + t] = 0;
        }
    }
}

// ---------------------------------------------------------------------------
// Kernel 2: ROI-align pooling (unchanged from R11 best): lane = x-sample,
// 4 channels in flight per warp, 8-way channel split.
// ---------------------------------------------------------------------------
__global__ void __launch_bounds__(256)
pool_kernel(const float* __restrict__ f0,
            const float* __restrict__ f1,
            const float* __restrict__ f2,
            const float* __restrict__ f3,
            float* __restrict__ out) {
    const int br   = blockIdx.x;        // b*R + r
    const int e    = blockIdx.y;        // channel eighth (0..7)
    const int b    = br / RR;
    const int tid  = threadIdx.x;
    const int w    = tid >> 5;          // warp 0..7
    const int lane = tid & 31;

    if (!g_sel_valid[br]) {
        if (tid < 32) out[(size_t)br * CC + e * 32 + tid] = 0.0f;
        return;
    }

    __shared__ float tWy[2 * GG], tWx[2 * GG];
    __shared__ int   tIy[2 * GG], tIx[2 * GG];
    __shared__ float cWy[2 * GG], cWx[2 * GG];
    __shared__ int   cOy[2 * GG], cIx[2 * GG];   // cOy = Iy * H (elements)
    __shared__ int   cnt[2];

    const float x1 = g_sel_boxes[(size_t)br * 4 + 0];
    const float y1 = g_sel_boxes[(size_t)br * 4 + 1];
    const float x2 = g_sel_boxes[(size_t)br * 4 + 2];
    const float y2 = g_sel_boxes[(size_t)br * 4 + 3];

    const float dx = x2 - x1, dy = y2 - y1;
    const float size = sqrtf(fmaxf(dx * dx + dy * dy, 1e-12f));
    const float lvf = floorf(4.0f + log2f(size * (4.0f / 224.0f)));
    const int lv = (int)(fminf(fmaxf(lvf, 2.0f), 5.0f)) - 2;

    const int H = 200 >> lv;            // 200, 100, 50, 25
    const int HH = H * H;
    const float Hf = (float)H;
    const float* F = (lv == 0) ? f0 : (lv == 1) ? f1 : (lv == 2) ? f2 : f3;

    const float rw = fmaxf(dx, 1.0f);
    const float rh = fmaxf(dy, 1.0f);

    if (tid < GG) {
        const float Yv = y1 + rh * ((tid + 0.5f) / (float)GG);
        const bool oob = (Yv < -1.0f) || (Yv > Hf);
        const float yc = fminf(fmaxf(Yv, 0.0f), Hf - 1.0f);
        const int y0 = (int)floorf(yc);
        const int yi1 = min(y0 + 1, H - 1);
        const float ly = yc - (float)y0;
        tIy[2 * tid]     = y0;  tWy[2 * tid]     = oob ? 0.0f : (1.0f - ly);
        tIy[2 * tid + 1] = yi1; tWy[2 * tid + 1] = oob ? 0.0f : ly;
    } else if (tid >= 32 && tid < 32 + GG) {
        const int a = tid - 32;
        const float Xv = x1 + rw * ((a + 0.5f) / (float)GG);
        const bool oob = (Xv < -1.0f) || (Xv > Hf);
        const float xc = fminf(fmaxf(Xv, 0.0f), Hf - 1.0f);
        const int x0 = (int)floorf(xc);
        const int xi1 = min(x0 + 1, H - 1);
        const float lx = xc - (float)x0;
        tIx[2 * a]     = x0;  tWx[2 * a]     = oob ? 0.0f : (1.0f - lx);
        tIx[2 * a + 1] = xi1; tWx[2 * a + 1] = oob ? 0.0f : lx;
    }
    __syncthreads();

    if (tid == 0) {
        int n = 0;
        for (int i = 0; i < 2 * GG; i++)
            if (tWy[i] != 0.0f) { cWy[n] = tWy[i]; cOy[n] = tIy[i] * H; n++; }
        cnt[0] = n;
    }
    if (tid == 32) {
        int n = 0;
        for (int i = 0; i < 2 * GG; i++)
            if (tWx[i] != 0.0f) { cWx[n] = tWx[i]; cIx[n] = tIx[i]; n++; }
        cnt[1] = n;
    }
    __syncthreads();

    const int ny = cnt[0], nx = cnt[1];
    const bool act = (lane < nx);
    const float wx = act ? cWx[lane] : 0.0f;
    const int   ix = act ? cIx[lane] : 0;

    float a0 = 0.0f, a1 = 0.0f, a2 = 0.0f, a3 = 0.0f;
    if (act) {
        const float* F0 = F + (size_t)(b * CC + e * 32 + w) * HH + ix;
        const float* F1 = F0 + (size_t)8  * HH;
        const float* F2 = F0 + (size_t)16 * HH;
        const float* F3 = F0 + (size_t)24 * HH;
        int i = 0;
        for (; i + 2 <= ny; i += 2) {
            const int o0 = cOy[i], o1 = cOy[i + 1];
            const float w0 = cWy[i], w1 = cWy[i + 1];
            a0 += w0 * __ldg(F0 + o0) + w1 * __ldg(F0 + o1);
            a1 += w0 * __ldg(F1 + o0) + w1 * __ldg(F1 + o1);
            a2 += w0 * __ldg(F2 + o0) + w1 * __ldg(F2 + o1);
            a3 += w0 * __ldg(F3 + o0) + w1 * __ldg(F3 + o1);
        }
        if (i < ny) {
            const int o0 = cOy[i];
            const float w0 = cWy[i];
            a0 += w0 * __ldg(F0 + o0);
            a1 += w0 * __ldg(F1 + o0);
            a2 += w0 * __ldg(F2 + o0);
            a3 += w0 * __ldg(F3 + o0);
        }
        a0 *= wx; a1 *= wx; a2 *= wx; a3 *= wx;
    }
#pragma unroll
    for (int o = 16; o; o >>= 1) {
        a0 += __shfl_xor_sync(0xffffffffu, a0, o);
        a1 += __shfl_xor_sync(0xffffffffu, a1, o);
        a2 += __shfl_xor_sync(0xffffffffu, a2, o);
        a3 += __shfl_xor_sync(0xffffffffu, a3, o);
    }
    if (lane == 0) {
        float* ob = out + (size_t)br * CC + e * 32 + w;
        ob[0]  = a0 * (1.0f / NSAMP);
        ob[8]  = a1 * (1.0f / NSAMP);
        ob[16] = a2 * (1.0f / NSAMP);
        ob[24] = a3 * (1.0f / NSAMP);
    }
}

// ---------------------------------------------------------------------------
extern "C" void kernel_launch(void* const* d_in, const int* in_sizes, int n_in,
                              void* d_out, int out_size) {
    const float* boxes  = (const float*)d_in[0];   // (B, N, 4)
    const float* scores = (const float*)d_in[1];   // (B, N)
    const float* feat0  = (const float*)d_in[2];   // (B, C, 200, 200)
    const float* feat1  = (const float*)d_in[3];   // (B, C, 100, 100)
    const float* feat2  = (const float*)d_in[4];   // (B, C, 50, 50)
    const float* feat3  = (const float*)d_in[5];   // (B, C, 25, 25)
    float* out = (float*)d_out;                    // (B, R, C)

    nms_rank_kernel<<<BB, 1024>>>(boxes, scores);
    nms_adj_kernel<<<dim3(BB, NWP), 320>>>();
    nms_greedy_kernel<<<BB, 512>>>();
    pool_kernel<<<dim3(BB * RR, 8), 256>>>(feat0, feat1, feat2, feat3, out);
}